// round 1
// baseline (speedup 1.0000x reference)
#include <cuda_runtime.h>
#include <cstdint>

#define AREAS 10
#define NPA   192
#define CDIM  128
#define NDIM  1920
#define MROWS 32768
#define OUTC  1280

// Scratch (allocation-free rule: __device__ globals)
__device__ float g_xg[(size_t)MROWS * NDIM];     // permuted, tf32-rounded x: xg[m][a*192+j]
__device__ float g_Wt[AREAS * NPA * CDIM];       // tf32-rounded W
__device__ int   g_src[NDIM];                    // src[a*192+j] = original column idx[a][j]

__device__ __forceinline__ float cvt_tf32(float v) {
    uint32_t u;
    asm("cvt.rna.tf32.f32 %0, %1;" : "=r"(u) : "f"(v));
    return __uint_as_float(u);
}

#define CP_ASYNC16(dst, src) \
    asm volatile("cp.async.cg.shared.global [%0], [%1], 16;" :: "r"(dst), "l"(src))
#define CP_COMMIT() asm volatile("cp.async.commit_group;" ::: "memory")
#define CP_WAIT0()  asm volatile("cp.async.wait_group 0;" ::: "memory")

// ---------------------------------------------------------------------------
// Build src[] : for each area a, the 192 column indices with label a, in order.
// 10 threads, each scans the 1920 labels (broadcast loads). Deterministic.
// ---------------------------------------------------------------------------
__global__ void setup_src_kernel(const int* __restrict__ nr) {
    int a = threadIdx.x;
    if (a < AREAS) {
        int cnt = 0;
        for (int n = 0; n < NDIM; n++) {
            if (nr[n] == a) { g_src[a * NPA + cnt] = n; cnt++; }
        }
    }
}

// tf32-round W once per launch
__global__ void wcvt_kernel(const float* __restrict__ W) {
    int i = blockIdx.x * 256 + threadIdx.x;
    if (i < AREAS * NPA * CDIM) g_Wt[i] = cvt_tf32(W[i]);
}

// ---------------------------------------------------------------------------
// Permute: xg[m][p] = tf32(x[m][src[p]]).
// Coalesced gmem read of 4 rows into SMEM, gather from SMEM, coalesced write.
// ---------------------------------------------------------------------------
__global__ __launch_bounds__(256)
void permute_kernel(const float* __restrict__ x) {
    __shared__ float srow[4 * NDIM];
    __shared__ int   ssrc[NDIM];
    const int tid = threadIdx.x;
    const size_t base = (size_t)blockIdx.x * 4 * NDIM;

    for (int i = tid; i < NDIM; i += 256) ssrc[i] = g_src[i];

    const float4* x4 = (const float4*)(x + base);
    float4* s4 = (float4*)srow;
    for (int i = tid; i < (4 * NDIM) / 4; i += 256) s4[i] = x4[i];
    __syncthreads();

    #pragma unroll
    for (int r = 0; r < 4; r++) {
        for (int p = tid; p < NDIM; p += 256) {
            g_xg[base + (size_t)r * NDIM + p] = cvt_tf32(srow[r * NDIM + ssrc[p]]);
        }
    }
}

// ---------------------------------------------------------------------------
// GEMM per (M-tile of 128, area): [128 x 192] @ [192 x 128] + bias, tf32 mma.
// 256 threads = 8 warps as 4(M) x 2(N); warp tile 32x64 = 2x8 m16n8k8 tiles.
// BK=16, cp.async double buffered.
// ---------------------------------------------------------------------------
__global__ __launch_bounds__(256, 2)
void gemm_kernel(const float* __restrict__ bias, float* __restrict__ out) {
    __shared__ float As[2][128 * 20];   // row stride 20 -> conflict-free frag loads
    __shared__ float Bs[2][16 * 132];   // row stride 132

    const int a    = blockIdx.y;
    const int m0   = blockIdx.x * 128;
    const int tid  = threadIdx.x;
    const int warp = tid >> 5, lane = tid & 31;
    const int wm = warp >> 1;           // 0..3 -> m offset wm*32
    const int wn = warp & 1;            // 0..1 -> n offset wn*64

    const float* Ag = g_xg + (size_t)m0 * NDIM + a * NPA;      // row stride NDIM
    const float* Bg = g_Wt + a * NPA * CDIM;                   // row stride CDIM

    float acc[2][8][4];
    #pragma unroll
    for (int i = 0; i < 2; i++)
        #pragma unroll
        for (int j = 0; j < 8; j++)
            #pragma unroll
            for (int k = 0; k < 4; k++) acc[i][j][k] = 0.f;

    auto load_stage = [&](int kt, int buf) {
        #pragma unroll
        for (int s = 0; s < 2; s++) {              // A tile: 512 float4
            int i = tid + s * 256;
            int row = i >> 2, k4 = i & 3;
            const float* src = Ag + (size_t)row * NDIM + kt * 16 + k4 * 4;
            uint32_t dst = (uint32_t)__cvta_generic_to_shared(&As[buf][row * 20 + k4 * 4]);
            CP_ASYNC16(dst, src);
        }
        #pragma unroll
        for (int s = 0; s < 2; s++) {              // B tile: 512 float4
            int i = tid + s * 256;
            int k = i >> 5, c4 = i & 31;
            const float* src = Bg + (kt * 16 + k) * CDIM + c4 * 4;
            uint32_t dst = (uint32_t)__cvta_generic_to_shared(&Bs[buf][k * 132 + c4 * 4]);
            CP_ASYNC16(dst, src);
        }
        CP_COMMIT();
    };

    load_stage(0, 0);

    for (int kt = 0; kt < 12; kt++) {
        const int buf = kt & 1;
        CP_WAIT0();
        __syncthreads();
        if (kt + 1 < 12) load_stage(kt + 1, buf ^ 1);

        #pragma unroll
        for (int k8 = 0; k8 < 2; k8++) {
            const int kk = k8 * 8;
            uint32_t af[2][4], bf[8][2];
            #pragma unroll
            for (int mt = 0; mt < 2; mt++) {
                int r = wm * 32 + mt * 16 + (lane >> 2);
                int c = kk + (lane & 3);
                af[mt][0] = __float_as_uint(As[buf][r * 20 + c]);
                af[mt][1] = __float_as_uint(As[buf][(r + 8) * 20 + c]);
                af[mt][2] = __float_as_uint(As[buf][r * 20 + c + 4]);
                af[mt][3] = __float_as_uint(As[buf][(r + 8) * 20 + c + 4]);
            }
            #pragma unroll
            for (int nt = 0; nt < 8; nt++) {
                int n  = wn * 64 + nt * 8 + (lane >> 2);
                int kr = kk + (lane & 3);
                bf[nt][0] = __float_as_uint(Bs[buf][kr * 132 + n]);
                bf[nt][1] = __float_as_uint(Bs[buf][(kr + 4) * 132 + n]);
            }
            #pragma unroll
            for (int mt = 0; mt < 2; mt++)
                #pragma unroll
                for (int nt = 0; nt < 8; nt++)
                    asm volatile(
                        "mma.sync.aligned.m16n8k8.row.col.f32.tf32.tf32.f32 "
                        "{%0,%1,%2,%3},{%4,%5,%6,%7},{%8,%9},{%0,%1,%2,%3};"
                        : "+f"(acc[mt][nt][0]), "+f"(acc[mt][nt][1]),
                          "+f"(acc[mt][nt][2]), "+f"(acc[mt][nt][3])
                        : "r"(af[mt][0]), "r"(af[mt][1]), "r"(af[mt][2]), "r"(af[mt][3]),
                          "r"(bf[nt][0]), "r"(bf[nt][1]));
        }
        __syncthreads();
    }

    // Epilogue: + bias, write float2 (32B-sector efficient: quad of lanes fills a sector)
    #pragma unroll
    for (int mt = 0; mt < 2; mt++) {
        const int r0 = m0 + wm * 32 + mt * 16 + (lane >> 2);
        #pragma unroll
        for (int nt = 0; nt < 8; nt++) {
            const int c  = wn * 64 + nt * 8 + (lane & 3) * 2;
            const float b0 = bias[a * CDIM + c];
            const float b1 = bias[a * CDIM + c + 1];
            float2 v0 = make_float2(acc[mt][nt][0] + b0, acc[mt][nt][1] + b1);
            float2 v1 = make_float2(acc[mt][nt][2] + b0, acc[mt][nt][3] + b1);
            *(float2*)(out + (size_t)r0 * OUTC + a * CDIM + c) = v0;
            *(float2*)(out + (size_t)(r0 + 8) * OUTC + a * CDIM + c) = v1;
        }
    }
}

// ---------------------------------------------------------------------------
extern "C" void kernel_launch(void* const* d_in, const int* in_sizes, int n_in,
                              void* d_out, int out_size) {
    const float* x    = (const float*)d_in[0];   // [32,1024,1920]
    const float* W    = (const float*)d_in[1];   // [10,192,128]
    const float* bias = (const float*)d_in[2];   // [10,128]
    const int*   nr   = (const int*)  d_in[3];   // [32,1920] (row 0 used)
    float* out = (float*)d_out;                  // [32,1024,1280]

    setup_src_kernel<<<1, 32>>>(nr);
    wcvt_kernel<<<(AREAS * NPA * CDIM + 255) / 256, 256>>>(W);
    permute_kernel<<<MROWS / 4, 256>>>(x);
    gemm_kernel<<<dim3(MROWS / 128, AREAS), 256>>>(bias, out);
}

// round 2
// speedup vs baseline: 1.0124x; 1.0124x over previous
#include <cuda_runtime.h>
#include <cstdint>

#define AREAS   10
#define NPA     192
#define CDIM    128
#define NDIM    1920
#define MROWS   32768
#define OUTC    1280
#define CHUNK_M 8192
#define NCHUNK  (MROWS / CHUNK_M)
#define STAGES  4

// Scratch: one L2-resident chunk (63MB), reused across chunks so lines stay hot.
__device__ float g_xg[(size_t)CHUNK_M * NDIM];
__device__ float g_Wt[AREAS * NPA * CDIM];
__device__ int   g_src[NDIM];

__device__ __forceinline__ float cvt_tf32(float v) {
    uint32_t u;
    asm("cvt.rna.tf32.f32 %0, %1;" : "=r"(u) : "f"(v));
    return __uint_as_float(u);
}

#define CP_ASYNC16(dst, src) \
    asm volatile("cp.async.cg.shared.global [%0], [%1], 16;" :: "r"(dst), "l"(src))
#define CP_COMMIT() asm volatile("cp.async.commit_group;" ::: "memory")
#define CP_WAIT2()  asm volatile("cp.async.wait_group 2;" ::: "memory")

// ---------------------------------------------------------------------------
// src[] via warp-ballot: warp a scans labels, stable order, ~2us.
// ---------------------------------------------------------------------------
__global__ void setup_src_kernel(const int* __restrict__ nr) {
    const int warp = threadIdx.x >> 5, lane = threadIdx.x & 31;
    if (warp < AREAS) {
        int cnt = 0;
        for (int base = 0; base < NDIM; base += 32) {
            const int n = base + lane;
            const bool m = (nr[n] == warp);
            const unsigned bal = __ballot_sync(0xffffffffu, m);
            if (m) g_src[warp * NPA + cnt + __popc(bal & ((1u << lane) - 1u))] = n;
            cnt += __popc(bal);
        }
    }
}

__global__ void wcvt_kernel(const float* __restrict__ W) {
    int i = blockIdx.x * 256 + threadIdx.x;
    if (i < AREAS * NPA * CDIM) g_Wt[i] = cvt_tf32(W[i]);
}

// ---------------------------------------------------------------------------
// Permute one chunk: xg[m][p] = tf32(x[chunk_row0+m][src[p]]), via SMEM staging.
// ---------------------------------------------------------------------------
__global__ __launch_bounds__(256)
void permute_kernel(const float* __restrict__ x, int chunk_row0) {
    __shared__ float srow[4 * NDIM];
    __shared__ int   ssrc[NDIM];
    const int tid = threadIdx.x;
    const size_t xbase  = ((size_t)chunk_row0 + blockIdx.x * 4) * NDIM;
    const size_t gbase  = (size_t)blockIdx.x * 4 * NDIM;

    for (int i = tid; i < NDIM; i += 256) ssrc[i] = g_src[i];

    const float4* x4 = (const float4*)(x + xbase);
    float4* s4 = (float4*)srow;
    for (int i = tid; i < (4 * NDIM) / 4; i += 256) s4[i] = x4[i];
    __syncthreads();

    #pragma unroll
    for (int r = 0; r < 4; r++)
        for (int p = tid; p < NDIM; p += 256)
            g_xg[gbase + (size_t)r * NDIM + p] = cvt_tf32(srow[r * NDIM + ssrc[p]]);
}

// ---------------------------------------------------------------------------
// GEMM per (M-tile 128, area): [128x192]@[192x128]+bias, tf32 mma,
// 4-stage cp.async pipeline, single barrier per k-iter.
// ---------------------------------------------------------------------------
#define AS_STRIDE 20
#define BS_STRIDE 132
#define AS_STAGE  (128 * AS_STRIDE)   // 2560 floats
#define BS_STAGE  (16 * BS_STRIDE)    // 2112 floats
#define SMEM_FLOATS (STAGES * (AS_STAGE + BS_STAGE))
#define SMEM_BYTES  (SMEM_FLOATS * 4) // 74752 B

__global__ __launch_bounds__(256, 2)
void gemm_kernel(const float* __restrict__ bias, float* __restrict__ out,
                 int chunk_row0) {
    extern __shared__ float smem[];
    float* As = smem;                         // [STAGES][AS_STAGE]
    float* Bs = smem + STAGES * AS_STAGE;     // [STAGES][BS_STAGE]

    const int a    = blockIdx.y;
    const int m0   = blockIdx.x * 128;        // within chunk
    const int tid  = threadIdx.x;
    const int warp = tid >> 5, lane = tid & 31;
    const int wm = warp >> 1;                 // 0..3
    const int wn = warp & 1;                  // 0..1

    const float* Ag = g_xg + (size_t)m0 * NDIM + a * NPA;
    const float* Bg = g_Wt + a * NPA * CDIM;

    float acc[2][8][4];
    #pragma unroll
    for (int i = 0; i < 2; i++)
        #pragma unroll
        for (int j = 0; j < 8; j++)
            #pragma unroll
            for (int k = 0; k < 4; k++) acc[i][j][k] = 0.f;

    auto load_stage = [&](int kt, int buf) {
        float* Ad = As + buf * AS_STAGE;
        float* Bd = Bs + buf * BS_STAGE;
        #pragma unroll
        for (int s = 0; s < 2; s++) {             // A: 512 float4
            int i = tid + s * 256;
            int row = i >> 2, k4 = i & 3;
            const float* src = Ag + (size_t)row * NDIM + kt * 16 + k4 * 4;
            uint32_t dst = (uint32_t)__cvta_generic_to_shared(&Ad[row * AS_STRIDE + k4 * 4]);
            CP_ASYNC16(dst, src);
        }
        #pragma unroll
        for (int s = 0; s < 2; s++) {             // B: 512 float4
            int i = tid + s * 256;
            int k = i >> 5, c4 = i & 31;
            const float* src = Bg + (kt * 16 + k) * CDIM + c4 * 4;
            uint32_t dst = (uint32_t)__cvta_generic_to_shared(&Bd[k * BS_STRIDE + c4 * 4]);
            CP_ASYNC16(dst, src);
        }
    };

    load_stage(0, 0); CP_COMMIT();
    load_stage(1, 1); CP_COMMIT();
    load_stage(2, 2); CP_COMMIT();

    #pragma unroll 1
    for (int kt = 0; kt < 12; kt++) {
        const int buf = kt & 3;
        CP_WAIT2();
        __syncthreads();
        if (kt + 3 < 12) load_stage(kt + 3, (kt + 3) & 3);
        CP_COMMIT();                              // empty commits keep the count law

        const float* Ab = As + buf * AS_STAGE;
        const float* Bb = Bs + buf * BS_STAGE;
        #pragma unroll
        for (int k8 = 0; k8 < 2; k8++) {
            const int kk = k8 * 8;
            uint32_t af[2][4], bf[8][2];
            #pragma unroll
            for (int mt = 0; mt < 2; mt++) {
                int r = wm * 32 + mt * 16 + (lane >> 2);
                int c = kk + (lane & 3);
                af[mt][0] = __float_as_uint(Ab[r * AS_STRIDE + c]);
                af[mt][1] = __float_as_uint(Ab[(r + 8) * AS_STRIDE + c]);
                af[mt][2] = __float_as_uint(Ab[r * AS_STRIDE + c + 4]);
                af[mt][3] = __float_as_uint(Ab[(r + 8) * AS_STRIDE + c + 4]);
            }
            #pragma unroll
            for (int nt = 0; nt < 8; nt++) {
                int n  = wn * 64 + nt * 8 + (lane >> 2);
                int kr = kk + (lane & 3);
                bf[nt][0] = __float_as_uint(Bb[kr * BS_STRIDE + n]);
                bf[nt][1] = __float_as_uint(Bb[(kr + 4) * BS_STRIDE + n]);
            }
            #pragma unroll
            for (int mt = 0; mt < 2; mt++)
                #pragma unroll
                for (int nt = 0; nt < 8; nt++)
                    asm volatile(
                        "mma.sync.aligned.m16n8k8.row.col.f32.tf32.tf32.f32 "
                        "{%0,%1,%2,%3},{%4,%5,%6,%7},{%8,%9},{%0,%1,%2,%3};"
                        : "+f"(acc[mt][nt][0]), "+f"(acc[mt][nt][1]),
                          "+f"(acc[mt][nt][2]), "+f"(acc[mt][nt][3])
                        : "r"(af[mt][0]), "r"(af[mt][1]), "r"(af[mt][2]), "r"(af[mt][3]),
                          "r"(bf[nt][0]), "r"(bf[nt][1]));
        }
    }

    #pragma unroll
    for (int mt = 0; mt < 2; mt++) {
        const int r0 = chunk_row0 + m0 + wm * 32 + mt * 16 + (lane >> 2);
        #pragma unroll
        for (int nt = 0; nt < 8; nt++) {
            const int c  = wn * 64 + nt * 8 + (lane & 3) * 2;
            const float b0 = bias[a * CDIM + c];
            const float b1 = bias[a * CDIM + c + 1];
            float2 v0 = make_float2(acc[mt][nt][0] + b0, acc[mt][nt][1] + b1);
            float2 v1 = make_float2(acc[mt][nt][2] + b0, acc[mt][nt][3] + b1);
            *(float2*)(out + (size_t)r0 * OUTC + a * CDIM + c) = v0;
            *(float2*)(out + (size_t)(r0 + 8) * OUTC + a * CDIM + c) = v1;
        }
    }
}

// ---------------------------------------------------------------------------
extern "C" void kernel_launch(void* const* d_in, const int* in_sizes, int n_in,
                              void* d_out, int out_size) {
    const float* x    = (const float*)d_in[0];
    const float* W    = (const float*)d_in[1];
    const float* bias = (const float*)d_in[2];
    const int*   nr   = (const int*)  d_in[3];
    float* out = (float*)d_out;

    static bool attr_set = false;
    if (!attr_set) {
        cudaFuncSetAttribute(gemm_kernel,
                             cudaFuncAttributeMaxDynamicSharedMemorySize, SMEM_BYTES);
        attr_set = true;
    }

    setup_src_kernel<<<1, 320>>>(nr);
    wcvt_kernel<<<(AREAS * NPA * CDIM + 255) / 256, 256>>>(W);

    for (int ch = 0; ch < NCHUNK; ch++) {
        const int row0 = ch * CHUNK_M;
        permute_kernel<<<CHUNK_M / 4, 256>>>(x, row0);
        gemm_kernel<<<dim3(CHUNK_M / 128, AREAS), 256, SMEM_BYTES>>>(bias, out, row0);
    }
}

// round 3
// speedup vs baseline: 1.1679x; 1.1537x over previous
#include <cuda_runtime.h>
#include <cstdint>

#define AREAS   10
#define NPA     192
#define CDIM    128
#define NDIM    1920
#define MROWS   32768
#define OUTC    1280
#define CHUNK_M 8192
#define NCHUNK  (MROWS / CHUNK_M)
#define KT      12                    // 12 k-chunks of 16
#define PR      8                     // rows per permute block

// xg layout: [(mb*AREAS+a)*KT + kt][r(128)][kr(4)][i(4)]  (floats)
__device__ float g_xg[(size_t)(CHUNK_M / 128) * AREAS * KT * 128 * 16];
// Wt layout: [a][kt][n(128)][kr(4)][i(4)]
__device__ float g_Wt[AREAS * KT * 128 * 16];
__device__ int   g_src[NDIM];
__device__ int   g_gperm[NDIM];       // gperm[((akt)*4+kr)*4+i] = src column

__device__ __forceinline__ float cvt_tf32(float v) {
    uint32_t u;
    asm("cvt.rna.tf32.f32 %0, %1;" : "=r"(u) : "f"(v));
    return __uint_as_float(u);
}

#define CP_ASYNC16(dst, src) \
    asm volatile("cp.async.cg.shared.global [%0], [%1], 16;" :: "r"(dst), "l"(src))
#define CP_COMMIT() asm volatile("cp.async.commit_group;" ::: "memory")
#define CP_WAIT0()  asm volatile("cp.async.wait_group 0;" ::: "memory")

// ---------------------------------------------------------------------------
__global__ void setup_src_kernel(const int* __restrict__ nr) {
    const int warp = threadIdx.x >> 5, lane = threadIdx.x & 31;
    if (warp < AREAS) {
        int cnt = 0;
        for (int base = 0; base < NDIM; base += 32) {
            const int n = base + lane;
            const bool m = (nr[n] == warp);
            const unsigned bal = __ballot_sync(0xffffffffu, m);
            if (m) g_src[warp * NPA + cnt + __popc(bal & ((1u << lane) - 1u))] = n;
            cnt += __popc(bal);
        }
    }
}

__global__ void gperm_kernel() {
    int q = blockIdx.x * 256 + threadIdx.x;   // q = ((a*12+kt)*4+kr)*4+i
    if (q < NDIM) {
        int i  = q & 3;
        int kr = (q >> 2) & 3;
        int akt = q >> 4;
        int a = akt / KT, kt = akt % KT;
        g_gperm[q] = g_src[a * NPA + kt * 16 + kr + 4 * i];
    }
}

// Wt[a][kt][n][kr][i] = tf32(W[a][kt*16+kr+4i][n])
__global__ void wcvt_kernel(const float* __restrict__ W) {
    int o = blockIdx.x * 256 + threadIdx.x;
    if (o < AREAS * KT * 128 * 16) {
        int i  = o & 3;
        int kr = (o >> 2) & 3;
        int n  = (o >> 4) & 127;
        int kt = (o >> 11) % KT;
        int a  = o / (KT * 128 * 16);
        int k  = kt * 16 + kr + 4 * i;
        g_Wt[o] = cvt_tf32(W[(a * NPA + k) * CDIM + n]);
    }
}

// ---------------------------------------------------------------------------
// Permute 8 rows: gather x via SMEM into fragment-order xg, float4 stores.
// ---------------------------------------------------------------------------
__global__ __launch_bounds__(256)
void permute_kernel(const float* __restrict__ x, int chunk_row0) {
    __shared__ float srow[PR * NDIM];
    __shared__ int   sg[NDIM];
    const int tid = threadIdx.x;
    const int r0   = blockIdx.x * PR;          // row within chunk
    const int mb   = r0 >> 7;                  // 128-row block
    const int rloc = r0 & 127;

    for (int i = tid; i < NDIM; i += 256) sg[i] = g_gperm[i];

    const float4* x4 = (const float4*)(x + ((size_t)chunk_row0 + r0) * NDIM);
    float4* s4 = (float4*)srow;
    #pragma unroll
    for (int s = 0; s < (PR * NDIM / 4) / 256; s++) s4[tid + s * 256] = x4[tid + s * 256];
    __syncthreads();

    // each t: one float4 store. c = (a*12+kt)*4+kr, row in 0..7
    #pragma unroll
    for (int s = 0; s < (PR * 480) / 256; s++) {
        int t = tid + s * 256;
        int row = t / 480;
        int c   = t % 480;                      // akt*4 + kr
        int kr  = c & 3, akt = c >> 2;
        const float* sr = srow + row * NDIM;
        const int* g = sg + c * 4;
        float4 v;
        v.x = cvt_tf32(sr[g[0]]);
        v.y = cvt_tf32(sr[g[1]]);
        v.z = cvt_tf32(sr[g[2]]);
        v.w = cvt_tf32(sr[g[3]]);
        float* dst = g_xg + ((size_t)mb * (AREAS * KT) + akt) * 2048
                          + (rloc + row) * 16 + kr * 4;
        *(float4*)dst = v;
    }
}

// ---------------------------------------------------------------------------
// GEMM: block = (128-row tile mb, area a). A direct LDG.128 from xg (L2),
// B whole-area slab in SMEM (98KB, fragment order). No A smem, 1 barrier.
// ---------------------------------------------------------------------------
#define B_SLAB_F (KT * 128 * 16)      // 24576 floats = 98304 B
#define SMEM_BYTES (B_SLAB_F * 4)

__global__ __launch_bounds__(256, 2)
void gemm_kernel(const float* __restrict__ bias, float* __restrict__ out,
                 int chunk_row0) {
    extern __shared__ float Bs[];
    const int a    = blockIdx.y;
    const int mb   = blockIdx.x;
    const int tid  = threadIdx.x;
    const int warp = tid >> 5, lane = tid & 31;
    const int wm = warp >> 1;                 // 0..3 : m offset wm*32
    const int wn = warp & 1;                  // 0..1 : n offset wn*64
    const int qr = lane >> 2;                 // 0..7
    const int kr = lane & 3;

    // load whole B slab for this area
    const float* Wsl = g_Wt + (size_t)a * B_SLAB_F;
    #pragma unroll
    for (int s = 0; s < (B_SLAB_F / 4) / 256; s++) {
        int i = tid + s * 256;
        uint32_t dst = (uint32_t)__cvta_generic_to_shared(Bs + i * 4);
        CP_ASYNC16(dst, Wsl + (size_t)i * 4);
    }
    CP_COMMIT();

    const float* Ag = g_xg + ((size_t)mb * AREAS + a) * KT * 2048;

    // prefetch A for kt=0 (4 x LDG.128), overlaps the cp.async slab load
    float4 areg[2][2];
    #pragma unroll
    for (int mt = 0; mt < 2; mt++)
        #pragma unroll
        for (int h = 0; h < 2; h++) {
            int r = wm * 32 + mt * 16 + h * 8 + qr;
            areg[mt][h] = *(const float4*)(Ag + r * 16 + kr * 4);
        }

    float acc[2][8][4];
    #pragma unroll
    for (int i = 0; i < 2; i++)
        #pragma unroll
        for (int j = 0; j < 8; j++)
            #pragma unroll
            for (int k = 0; k < 4; k++) acc[i][j][k] = 0.f;

    CP_WAIT0();
    __syncthreads();

    #pragma unroll
    for (int kt = 0; kt < KT; kt++) {
        float4 curA[2][2];
        #pragma unroll
        for (int mt = 0; mt < 2; mt++)
            #pragma unroll
            for (int h = 0; h < 2; h++) curA[mt][h] = areg[mt][h];

        if (kt + 1 < KT) {
            const float* An = Ag + (kt + 1) * 2048;
            #pragma unroll
            for (int mt = 0; mt < 2; mt++)
                #pragma unroll
                for (int h = 0; h < 2; h++) {
                    int r = wm * 32 + mt * 16 + h * 8 + qr;
                    areg[mt][h] = *(const float4*)(An + r * 16 + kr * 4);
                }
        }

        // B fragments: 8 conflict-free LDS.128
        float4 bfr[8];
        #pragma unroll
        for (int nt = 0; nt < 8; nt++) {
            int n = wn * 64 + nt * 8 + qr;
            bfr[nt] = *(const float4*)(Bs + (kt * 128 + n) * 16 + kr * 4);
        }

        #pragma unroll
        for (int k8 = 0; k8 < 2; k8++) {
            #pragma unroll
            for (int mt = 0; mt < 2; mt++) {
                uint32_t a0, a1, a2, a3;
                if (k8 == 0) {
                    a0 = __float_as_uint(curA[mt][0].x);
                    a1 = __float_as_uint(curA[mt][1].x);
                    a2 = __float_as_uint(curA[mt][0].y);
                    a3 = __float_as_uint(curA[mt][1].y);
                } else {
                    a0 = __float_as_uint(curA[mt][0].z);
                    a1 = __float_as_uint(curA[mt][1].z);
                    a2 = __float_as_uint(curA[mt][0].w);
                    a3 = __float_as_uint(curA[mt][1].w);
                }
                #pragma unroll
                for (int nt = 0; nt < 8; nt++) {
                    uint32_t b0 = __float_as_uint(k8 == 0 ? bfr[nt].x : bfr[nt].z);
                    uint32_t b1 = __float_as_uint(k8 == 0 ? bfr[nt].y : bfr[nt].w);
                    asm volatile(
                        "mma.sync.aligned.m16n8k8.row.col.f32.tf32.tf32.f32 "
                        "{%0,%1,%2,%3},{%4,%5,%6,%7},{%8,%9},{%0,%1,%2,%3};"
                        : "+f"(acc[mt][nt][0]), "+f"(acc[mt][nt][1]),
                          "+f"(acc[mt][nt][2]), "+f"(acc[mt][nt][3])
                        : "r"(a0), "r"(a1), "r"(a2), "r"(a3), "r"(b0), "r"(b1));
                }
            }
        }
    }

    #pragma unroll
    for (int mt = 0; mt < 2; mt++) {
        const int r0g = chunk_row0 + mb * 128 + wm * 32 + mt * 16 + qr;
        #pragma unroll
        for (int nt = 0; nt < 8; nt++) {
            const int c  = wn * 64 + nt * 8 + kr * 2;
            const float b0 = bias[a * CDIM + c];
            const float b1 = bias[a * CDIM + c + 1];
            float2 v0 = make_float2(acc[mt][nt][0] + b0, acc[mt][nt][1] + b1);
            float2 v1 = make_float2(acc[mt][nt][2] + b0, acc[mt][nt][3] + b1);
            *(float2*)(out + (size_t)r0g * OUTC + a * CDIM + c) = v0;
            *(float2*)(out + (size_t)(r0g + 8) * OUTC + a * CDIM + c) = v1;
        }
    }
}

// ---------------------------------------------------------------------------
extern "C" void kernel_launch(void* const* d_in, const int* in_sizes, int n_in,
                              void* d_out, int out_size) {
    const float* x    = (const float*)d_in[0];
    const float* W    = (const float*)d_in[1];
    const float* bias = (const float*)d_in[2];
    const int*   nr   = (const int*)  d_in[3];
    float* out = (float*)d_out;

    static bool attr_set = false;
    if (!attr_set) {
        cudaFuncSetAttribute(gemm_kernel,
                             cudaFuncAttributeMaxDynamicSharedMemorySize, SMEM_BYTES);
        attr_set = true;
    }

    setup_src_kernel<<<1, 320>>>(nr);
    gperm_kernel<<<(NDIM + 255) / 256, 256>>>();
    wcvt_kernel<<<(AREAS * KT * 128 * 16 + 255) / 256, 256>>>(W);

    for (int ch = 0; ch < NCHUNK; ch++) {
        const int row0 = ch * CHUNK_M;
        permute_kernel<<<CHUNK_M / PR, 256>>>(x, row0);
        gemm_kernel<<<dim3(CHUNK_M / 128, AREAS), 256, SMEM_BYTES>>>(bias, out, row0);
    }
}